// round 1
// baseline (speedup 1.0000x reference)
#include <cuda_runtime.h>
#include <cstdint>
#include <math.h>

#define FDIM 1024
#define HDIM 64
#define NTOK 32768

// Scratch (allocation-free rule: device globals)
static __device__ float g_H[(size_t)NTOK * 320];   // relu(fc1) for branches 0..4
static __device__ float g_H5[(size_t)NTOK * 64];   // relu(fc1) for branch 5

// ---------------- helpers ----------------
__device__ __forceinline__ uint32_t f2t(float f) {
    uint32_t r;
    asm("cvt.rna.tf32.f32 %0, %1;" : "=r"(r) : "f"(f));
    return r;
}

__device__ __forceinline__ void mma8(float* c, uint32_t a0, uint32_t a1, uint32_t a2, uint32_t a3,
                                     uint32_t b0, uint32_t b1) {
    asm volatile(
        "mma.sync.aligned.m16n8k8.row.col.f32.tf32.tf32.f32 "
        "{%0,%1,%2,%3},{%4,%5,%6,%7},{%8,%9},{%0,%1,%2,%3};"
        : "+f"(c[0]), "+f"(c[1]), "+f"(c[2]), "+f"(c[3])
        : "r"(a0), "r"(a1), "r"(a2), "r"(a3), "r"(b0), "r"(b1));
}

__device__ __forceinline__ uint32_t saddr(const void* p) {
    return (uint32_t)__cvta_generic_to_shared(p);
}
__device__ __forceinline__ void cp16(uint32_t s, const void* g) {
    asm volatile("cp.async.ca.shared.global [%0], [%1], 16;" :: "r"(s), "l"(g));
}
__device__ __forceinline__ void cp_commit() { asm volatile("cp.async.commit_group;"); }
__device__ __forceinline__ void cp_wait0() { asm volatile("cp.async.wait_group 0;"); }
__device__ __forceinline__ void cp_wait1() { asm volatile("cp.async.wait_group 1;"); }

__device__ __forceinline__ float softplus_f(float v) {
    return fmaxf(v, 0.f) + log1pf(__expf(-fabsf(v)));
}
__device__ __forceinline__ float sigmoid_f(float v) {
    return 1.f / (1.f + __expf(-v));
}

// =====================================================================
// Kernel A: H[N,320] = relu(x @ W1cat[1024,320] + B1cat)  (branches 0..4)
// BM=64, BN=320, BK=32, 512 threads, warp grid 4(M)x4(N), warp tile 16x80
// =====================================================================
#define A_SXP 36
#define A_SWP 328
#define A_SXSZ (64 * A_SXP)
#define A_BUF (A_SXSZ + 32 * A_SWP)   // floats per buffer = 12800

__global__ void __launch_bounds__(512, 1)
k_fc1_all(const float* __restrict__ x, const float* __restrict__ W1,
          const float* __restrict__ B1, int N) {
    extern __shared__ float sm[];
    int tid = threadIdx.x;
    int lane = tid & 31, warp = tid >> 5;
    int g = lane >> 2, t = lane & 3;
    int wm = warp >> 2, wn = warp & 3;
    long rowBase = (long)blockIdx.x * 64;
    const float* xb = x + rowBase * FDIM;

    float acc[40];
#pragma unroll
    for (int i = 0; i < 40; i++) acc[i] = 0.f;

    auto issue = [&](int it, int bi) {
        float* sx = sm + bi * A_BUF;
        float* sw = sx + A_SXSZ;
        int k0 = it * 32;
        {
            int r = tid >> 3, seg = tid & 7;
            cp16(saddr(sx + r * A_SXP + seg * 4), xb + (long)r * FDIM + k0 + seg * 4);
        }
#pragma unroll
        for (int j = 0; j < 5; j++) {
            int idx = j * 512 + tid;
            int m = idx >> 9, rem = idx & 511;
            int k = rem >> 4, seg = rem & 15;
            cp16(saddr(sw + k * A_SWP + m * 64 + seg * 4),
                 W1 + ((long)m * FDIM + (k0 + k)) * HDIM + seg * 4);
        }
        cp_commit();
    };

    auto compute = [&](int bi) {
        const float* sx = sm + bi * A_BUF;
        const float* sw = sx + A_SXSZ;
#pragma unroll
        for (int ks = 0; ks < 4; ks++) {
            int kb = ks * 8;
            const float* ap = sx + (wm * 16 + g) * A_SXP + kb + t;
            uint32_t a0 = f2t(ap[0]), a1 = f2t(ap[8 * A_SXP]);
            uint32_t a2 = f2t(ap[4]), a3 = f2t(ap[8 * A_SXP + 4]);
#pragma unroll
            for (int nt = 0; nt < 10; nt++) {
                int c = wn * 80 + nt * 8 + g;
                uint32_t b0 = f2t(sw[(kb + t) * A_SWP + c]);
                uint32_t b1 = f2t(sw[(kb + t + 4) * A_SWP + c]);
                mma8(acc + nt * 4, a0, a1, a2, a3, b0, b1);
            }
        }
    };

    const int NK = FDIM / 32;   // 32
    issue(0, 0);
    for (int it = 0; it < NK; ++it) {
        if (it + 1 < NK) { issue(it + 1, (it + 1) & 1); cp_wait1(); }
        else             { cp_wait0(); }
        __syncthreads();
        compute(it & 1);
        __syncthreads();
    }

    long r0 = rowBase + wm * 16 + g;
#pragma unroll
    for (int nt = 0; nt < 10; nt++) {
        int col = wn * 80 + nt * 8 + 2 * t;
        float bb0 = B1[col], bb1 = B1[col + 1];
        float2 v;
        v.x = fmaxf(acc[nt * 4 + 0] + bb0, 0.f);
        v.y = fmaxf(acc[nt * 4 + 1] + bb1, 0.f);
        *(float2*)(g_H + r0 * 320 + col) = v;
        v.x = fmaxf(acc[nt * 4 + 2] + bb0, 0.f);
        v.y = fmaxf(acc[nt * 4 + 3] + bb1, 0.f);
        *(float2*)(g_H + (r0 + 8) * 320 + col) = v;
    }
}

// =====================================================================
// Kernel B: for m in 0..4: out[m] = act_m(x + H_m @ W2_m + B2_m)
// Tile: 64 tokens x 256 features. 256 threads, warp grid 2(M)x4(N).
// =====================================================================
#define B_SHP 68
#define B_SWP 264
#define B_SHSZ (64 * B_SHP)
#define B_BUF (B_SHSZ + 64 * B_SWP)   // floats per buffer = 21248

__global__ void __launch_bounds__(256, 1)
k_fc2_all(const float* __restrict__ x, const float* __restrict__ W2,
          const float* __restrict__ B2, float* __restrict__ out, int N) {
    extern __shared__ float sm[];
    int tid = threadIdx.x;
    int lane = tid & 31, warp = tid >> 5;
    int g = lane >> 2, t = lane & 3;
    int wm = warp >> 2, wn = warp & 3;
    long rowBase = (long)blockIdx.x * 64;
    int fbase = blockIdx.y * 256;

    auto issue = [&](int m, int bi) {
        float* sh = sm + bi * B_BUF;
        float* sw = sh + B_SHSZ;
#pragma unroll
        for (int j = 0; j < 4; j++) {
            int idx = j * 256 + tid;
            int r = idx >> 4, seg = idx & 15;
            cp16(saddr(sh + r * B_SHP + seg * 4),
                 g_H + (rowBase + r) * 320 + m * 64 + seg * 4);
        }
#pragma unroll
        for (int j = 0; j < 16; j++) {
            int idx = j * 256 + tid;
            int h = idx >> 6, seg = idx & 63;
            cp16(saddr(sw + h * B_SWP + seg * 4),
                 W2 + ((long)(m * 64 + h)) * FDIM + fbase + seg * 4);
        }
        cp_commit();
    };

    issue(0, 0);
    for (int m = 0; m < 5; ++m) {
        if (m + 1 < 5) { issue(m + 1, (m + 1) & 1); cp_wait1(); }
        else           { cp_wait0(); }
        __syncthreads();
        const float* sh = sm + (m & 1) * B_BUF;
        const float* sw = sh + B_SHSZ;

        float acc[2][8][4];
#pragma unroll
        for (int a = 0; a < 2; a++)
#pragma unroll
            for (int b = 0; b < 8; b++)
#pragma unroll
                for (int c = 0; c < 4; c++) acc[a][b][c] = 0.f;

#pragma unroll
        for (int ks = 0; ks < 8; ks++) {
            int kb = ks * 8;
            uint32_t af[2][4];
#pragma unroll
            for (int mt = 0; mt < 2; mt++) {
                const float* ap = sh + (wm * 32 + mt * 16 + g) * B_SHP + kb + t;
                af[mt][0] = f2t(ap[0]);
                af[mt][1] = f2t(ap[8 * B_SHP]);
                af[mt][2] = f2t(ap[4]);
                af[mt][3] = f2t(ap[8 * B_SHP + 4]);
            }
#pragma unroll
            for (int nt = 0; nt < 8; nt++) {
                int c = wn * 64 + nt * 8 + g;
                uint32_t b0 = f2t(sw[(kb + t) * B_SWP + c]);
                uint32_t b1 = f2t(sw[(kb + t + 4) * B_SWP + c]);
                mma8(acc[0][nt], af[0][0], af[0][1], af[0][2], af[0][3], b0, b1);
                mma8(acc[1][nt], af[1][0], af[1][1], af[1][2], af[1][3], b0, b1);
            }
        }

#pragma unroll
        for (int mt = 0; mt < 2; mt++) {
            long row = rowBase + wm * 32 + mt * 16 + g;
#pragma unroll
            for (int nt = 0; nt < 8; nt++) {
                int col = fbase + wn * 64 + nt * 8 + 2 * t;
                float bb0 = B2[m * FDIM + col], bb1 = B2[m * FDIM + col + 1];
#pragma unroll
                for (int rr = 0; rr < 2; rr++) {
                    long rw = row + rr * 8;
                    float2 xv = *(const float2*)(x + rw * FDIM + col);
                    float v0 = acc[mt][nt][rr * 2 + 0] + xv.x + bb0;
                    float v1 = acc[mt][nt][rr * 2 + 1] + xv.y + bb1;
                    if (m == 3)      { v0 = softplus_f(v0); v1 = softplus_f(v1); }
                    else if (m == 4) { v0 = sigmoid_f(v0);  v1 = sigmoid_f(v1);  }
                    float2 o; o.x = v0; o.y = v1;
                    *(float2*)(out + ((long)m * N + rw) * FDIM + col) = o;
                }
            }
        }
        __syncthreads();
    }
}

// =====================================================================
// Kernel C: H5[N,64] = relu(q @ W1[5] + B1[5]);  q = out slot 2
// BM=128, BN=64, BK=32, 256 threads, 8 warps each a 16x64 tile.
// =====================================================================
#define C_SQP 36
#define C_SWP 72
#define C_SQSZ (128 * C_SQP)
#define C_BUF (C_SQSZ + 32 * C_SWP)   // floats per buffer = 6912

__global__ void __launch_bounds__(256, 1)
k_fc1_mem(const float* __restrict__ out, const float* __restrict__ W1,
          const float* __restrict__ B1, int N) {
    extern __shared__ float sm[];
    const float* q = out + 2ll * N * FDIM;
    int tid = threadIdx.x;
    int lane = tid & 31, warp = tid >> 5;
    int g = lane >> 2, t = lane & 3;
    long rowBase = (long)blockIdx.x * 128;

    float acc[32];
#pragma unroll
    for (int i = 0; i < 32; i++) acc[i] = 0.f;

    auto issue = [&](int it, int bi) {
        float* sq = sm + bi * C_BUF;
        float* sw = sq + C_SQSZ;
        int k0 = it * 32;
#pragma unroll
        for (int j = 0; j < 4; j++) {
            int idx = j * 256 + tid;
            int r = idx >> 3, seg = idx & 7;
            cp16(saddr(sq + r * C_SQP + seg * 4),
                 q + (rowBase + r) * FDIM + k0 + seg * 4);
        }
#pragma unroll
        for (int j = 0; j < 2; j++) {
            int idx = j * 256 + tid;
            int k = idx >> 4, seg = idx & 15;
            cp16(saddr(sw + k * C_SWP + seg * 4),
                 W1 + (5ll * FDIM + k0 + k) * HDIM + seg * 4);
        }
        cp_commit();
    };

    auto compute = [&](int bi) {
        const float* sq = sm + bi * C_BUF;
        const float* sw = sq + C_SQSZ;
#pragma unroll
        for (int ks = 0; ks < 4; ks++) {
            int kb = ks * 8;
            const float* ap = sq + (warp * 16 + g) * C_SQP + kb + t;
            uint32_t a0 = f2t(ap[0]), a1 = f2t(ap[8 * C_SQP]);
            uint32_t a2 = f2t(ap[4]), a3 = f2t(ap[8 * C_SQP + 4]);
#pragma unroll
            for (int nt = 0; nt < 8; nt++) {
                int c = nt * 8 + g;
                uint32_t b0 = f2t(sw[(kb + t) * C_SWP + c]);
                uint32_t b1 = f2t(sw[(kb + t + 4) * C_SWP + c]);
                mma8(acc + nt * 4, a0, a1, a2, a3, b0, b1);
            }
        }
    };

    const int NK = FDIM / 32;
    issue(0, 0);
    for (int it = 0; it < NK; ++it) {
        if (it + 1 < NK) { issue(it + 1, (it + 1) & 1); cp_wait1(); }
        else             { cp_wait0(); }
        __syncthreads();
        compute(it & 1);
        __syncthreads();
    }

    long r0 = rowBase + warp * 16 + g;
#pragma unroll
    for (int nt = 0; nt < 8; nt++) {
        int col = nt * 8 + 2 * t;
        float bb0 = B1[320 + col], bb1 = B1[320 + col + 1];
        float2 v;
        v.x = fmaxf(acc[nt * 4 + 0] + bb0, 0.f);
        v.y = fmaxf(acc[nt * 4 + 1] + bb1, 0.f);
        *(float2*)(g_H5 + r0 * 64 + col) = v;
        v.x = fmaxf(acc[nt * 4 + 2] + bb0, 0.f);
        v.y = fmaxf(acc[nt * 4 + 3] + bb1, 0.f);
        *(float2*)(g_H5 + (r0 + 8) * 64 + col) = v;
    }
}

// =====================================================================
// Kernel D: out[5] = x + q + H5 @ W2[5] + B2[5]
// Same tiling as kernel B, single branch.
// =====================================================================
__global__ void __launch_bounds__(256, 1)
k_fc2_mem(const float* __restrict__ x, const float* __restrict__ W2,
          const float* __restrict__ B2, float* __restrict__ out, int N) {
    extern __shared__ float sm[];
    int tid = threadIdx.x;
    int lane = tid & 31, warp = tid >> 5;
    int g = lane >> 2, t = lane & 3;
    int wm = warp >> 2, wn = warp & 3;
    long rowBase = (long)blockIdx.x * 64;
    int fbase = blockIdx.y * 256;
    const float* q = out + 2ll * N * FDIM;

    float* sh = sm;
    float* sw = sm + B_SHSZ;
#pragma unroll
    for (int j = 0; j < 4; j++) {
        int idx = j * 256 + tid;
        int r = idx >> 4, seg = idx & 15;
        cp16(saddr(sh + r * B_SHP + seg * 4),
             g_H5 + (rowBase + r) * 64 + seg * 4);
    }
#pragma unroll
    for (int j = 0; j < 16; j++) {
        int idx = j * 256 + tid;
        int h = idx >> 6, seg = idx & 63;
        cp16(saddr(sw + h * B_SWP + seg * 4),
             W2 + (5ll * 64 + h) * FDIM + fbase + seg * 4);
    }
    cp_commit();
    cp_wait0();
    __syncthreads();

    float acc[2][8][4];
#pragma unroll
    for (int a = 0; a < 2; a++)
#pragma unroll
        for (int b = 0; b < 8; b++)
#pragma unroll
            for (int c = 0; c < 4; c++) acc[a][b][c] = 0.f;

#pragma unroll
    for (int ks = 0; ks < 8; ks++) {
        int kb = ks * 8;
        uint32_t af[2][4];
#pragma unroll
        for (int mt = 0; mt < 2; mt++) {
            const float* ap = sh + (wm * 32 + mt * 16 + g) * B_SHP + kb + t;
            af[mt][0] = f2t(ap[0]);
            af[mt][1] = f2t(ap[8 * B_SHP]);
            af[mt][2] = f2t(ap[4]);
            af[mt][3] = f2t(ap[8 * B_SHP + 4]);
        }
#pragma unroll
        for (int nt = 0; nt < 8; nt++) {
            int c = wn * 64 + nt * 8 + g;
            uint32_t b0 = f2t(sw[(kb + t) * B_SWP + c]);
            uint32_t b1 = f2t(sw[(kb + t + 4) * B_SWP + c]);
            mma8(acc[0][nt], af[0][0], af[0][1], af[0][2], af[0][3], b0, b1);
            mma8(acc[1][nt], af[1][0], af[1][1], af[1][2], af[1][3], b0, b1);
        }
    }

#pragma unroll
    for (int mt = 0; mt < 2; mt++) {
        long row = rowBase + wm * 32 + mt * 16 + g;
#pragma unroll
        for (int nt = 0; nt < 8; nt++) {
            int col = fbase + wn * 64 + nt * 8 + 2 * t;
            float bb0 = B2[5 * FDIM + col], bb1 = B2[5 * FDIM + col + 1];
#pragma unroll
            for (int rr = 0; rr < 2; rr++) {
                long rw = row + rr * 8;
                float2 xv = *(const float2*)(x + rw * FDIM + col);
                float2 qv = *(const float2*)(q + rw * FDIM + col);
                float2 o;
                o.x = acc[mt][nt][rr * 2 + 0] + xv.x + qv.x + bb0;
                o.y = acc[mt][nt][rr * 2 + 1] + xv.y + qv.y + bb1;
                *(float2*)(out + (5ll * N + rw) * FDIM + col) = o;
            }
        }
    }
}

// =====================================================================
extern "C" void kernel_launch(void* const* d_in, const int* in_sizes, int n_in,
                              void* d_out, int out_size) {
    const float* x  = (const float*)d_in[0];
    const float* W1 = (const float*)d_in[1];
    const float* B1 = (const float*)d_in[2];
    const float* W2 = (const float*)d_in[3];
    const float* B2 = (const float*)d_in[4];
    float* out = (float*)d_out;
    int N = in_sizes[0] / FDIM;

    const int A_SMEM = 2 * A_BUF * (int)sizeof(float);   // 102400
    const int B_SMEM = 2 * B_BUF * (int)sizeof(float);   // 169984
    const int C_SMEM = 2 * C_BUF * (int)sizeof(float);   //  55296
    const int D_SMEM = B_BUF * (int)sizeof(float);       //  84992

    cudaFuncSetAttribute(k_fc1_all, cudaFuncAttributeMaxDynamicSharedMemorySize, A_SMEM);
    cudaFuncSetAttribute(k_fc2_all, cudaFuncAttributeMaxDynamicSharedMemorySize, B_SMEM);
    cudaFuncSetAttribute(k_fc1_mem, cudaFuncAttributeMaxDynamicSharedMemorySize, C_SMEM);
    cudaFuncSetAttribute(k_fc2_mem, cudaFuncAttributeMaxDynamicSharedMemorySize, D_SMEM);

    k_fc1_all<<<N / 64, 512, A_SMEM>>>(x, W1, B1, N);
    k_fc2_all<<<dim3(N / 64, FDIM / 256), 256, B_SMEM>>>(x, W2, B2, out, N);
    k_fc1_mem<<<N / 128, 256, C_SMEM>>>(out, W1, B1, N);
    k_fc2_mem<<<dim3(N / 64, FDIM / 256), 256, D_SMEM>>>(x, W2, B2, out, N);
}